// round 10
// baseline (speedup 1.0000x reference)
#include <cuda_runtime.h>
#include <stdint.h>

#define BN 64
#define GN 4999
#define PN 50
#define NPOS 5120          // padded positions = 32*160
#define NWRD 160           // mask words per pathway
#define SEGK 160           // positions per lane
#define NPAD 121           // NPOS - GN
#define NSPL 4             // range splits per sample
#define MAXB 3456          // max buckets per range (padded for scan)
#define MAXE 2048          // max elements per range (mean 1250, 26 sigma margin)

__device__ __align__(16) unsigned d_gbits[2 * GN];   // gene-major pathway bits
__device__ __align__(16) float    d_sw[BN * NPOS];   // sorted |x|^.25
__device__ __align__(16) uint2    d_h01[BN * NPOS];  // gathered pathway words per position

// bucket range splits at normal quartiles x = {+inf, .6745, 0, -.6745, -inf}
__constant__ int c_r[NSPL + 1] = {0, 3405, 4096, 4787, 8192};

// ---------------------------------------------------------------------------
// K1: gene-major pathway bits via warp ballot transpose.
// Warp covers 32 consecutive genes; 50 coalesced loads, each lane extracts
// its own gene's bit from the ballot. grid 20 x 256 (157 active warps).
// ---------------------------------------------------------------------------
__global__ void pbuild_kernel(const float* __restrict__ pw) {
    const int warp = (blockIdx.x * blockDim.x + threadIdx.x) >> 5;
    const int lane = threadIdx.x & 31;
    if (warp >= (GN + 31) / 32) return;
    const int g = warp * 32 + lane;
    const bool valid = g < GN;
    unsigned w0 = 0, w1 = 0;
    #pragma unroll
    for (int p = 0; p < 32; p++) {
        float v = valid ? pw[(size_t)p * GN + g] : 0.0f;
        unsigned bl = __ballot_sync(0xffffffffu, v > 0.0f);
        w0 |= ((bl >> lane) & 1u) << p;
    }
    #pragma unroll
    for (int p = 32; p < PN; p++) {
        float v = valid ? pw[(size_t)p * GN + g] : 0.0f;
        unsigned bl = __ballot_sync(0xffffffffu, v > 0.0f);
        w1 |= ((bl >> lane) & 1u) << (p - 32);
    }
    if (valid) {
        d_gbits[2 * g]     = w0;
        d_gbits[2 * g + 1] = w1;
    }
}

// ---------------------------------------------------------------------------
// K2: range-split bucket sort. Grid (BN, NSPL) x 512. Block (b, r) loads the
// full row, derives its global base = count(bucket < rlo) locally, sorts only
// buckets [rlo, rhi), and writes w + pre-gathered pathway words.
// ---------------------------------------------------------------------------
#define ST 512
#define EPT 10             // ceil(4999/512)

__global__ void __launch_bounds__(ST)
sort_kernel(const float* __restrict__ expr) {
    __shared__ unsigned s_hist[3584];            // owned-bin scan layout (7/thread)
    __shared__ unsigned long long s_keys[MAXE];
    __shared__ unsigned s_red[16];

    const int b    = blockIdx.x;
    const int r    = blockIdx.y;
    const int tid  = threadIdx.x;
    const int wid  = tid >> 5;
    const int lane = tid & 31;
    const int rlo  = c_r[r];
    const int rhi  = c_r[r + 1];
    const int nb   = rhi - rlo;
    const float* row = expr + (size_t)b * GN;

    for (int i = tid; i < 3584; i += ST) s_hist[i] = 0;
    __syncthreads();

    // ---- load full row, bucket, histogram own range, count below ----
    unsigned long long key[EPT];
    int bkt[EPT];
    int below = 0;
    #pragma unroll
    for (int j = 0; j < EPT; j++) {
        int i = j * ST + tid;
        if (i < GN) {
            float x = row[i];
            unsigned u = __float_as_uint(x);
            u = (u & 0x80000000u) ? ~u : (u | 0x80000000u);   // ascending map
            key[j] = ((unsigned long long)(~u) << 13) | (unsigned)i;
            int bb = (int)((4.0f - x) * 1024.0f);
            bb = bb < 0 ? 0 : (bb > 8191 ? 8191 : bb);
            bkt[j] = bb;
            below += (bb < rlo);
            if (bb >= rlo && bb < rhi) atomicAdd(&s_hist[bb - rlo], 1u);
        } else {
            bkt[j] = -1;
        }
    }

    // ---- block reduce 'below' -> base ----
    #pragma unroll
    for (int off = 16; off; off >>= 1) below += __shfl_down_sync(0xffffffffu, below, off);
    if (lane == 0) s_red[wid] = (unsigned)below;
    __syncthreads();
    int base = 0;
    #pragma unroll
    for (int q = 0; q < 16; q++) base += (int)s_red[q];
    __syncthreads();                              // s_red reused below

    // ---- exclusive scan over owned bins (7 per thread) ----
    {
        unsigned h[7], lsum = 0;
        #pragma unroll
        for (int q = 0; q < 7; q++) { h[q] = s_hist[tid * 7 + q]; lsum += h[q]; }
        unsigned v = lsum;
        #pragma unroll
        for (int off = 1; off < 32; off <<= 1) {
            unsigned n = __shfl_up_sync(0xffffffffu, v, off);
            if (lane >= off) v += n;
        }
        if (lane == 31) s_red[wid] = v;
        __syncthreads();
        if (wid == 0 && lane < 16) {
            unsigned wv = s_red[lane];
            unsigned vv = wv;
            #pragma unroll
            for (int off = 1; off < 16; off <<= 1) {
                unsigned n = __shfl_up_sync(0x0000ffffu, vv, off);
                if (lane >= off) vv += n;
            }
            s_red[lane] = vv - wv;                // exclusive warp bases
        }
        __syncthreads();
        unsigned run = s_red[wid] + (v - lsum);
        #pragma unroll
        for (int q = 0; q < 7; q++) { s_hist[tid * 7 + q] = run; run += h[q]; }
    }
    __syncthreads();

    // ---- scatter own elements ----
    #pragma unroll
    for (int j = 0; j < EPT; j++) {
        if (bkt[j] >= rlo && bkt[j] < rhi) {
            unsigned p = atomicAdd(&s_hist[bkt[j] - rlo], 1u);
            if (p < MAXE) s_keys[p] = key[j];
        }
    }
    __syncthreads();
    int n = (int)s_hist[nb - 1];                  // end of last own bucket
    if (n > MAXE) n = MAXE;

    // ---- insertion sort within buckets (full unique key) ----
    #pragma unroll 1
    for (int q = 0; q < 7; q++) {
        int bb = tid * 7 + q;
        if (bb >= nb) break;
        int st = (bb == 0) ? 0 : (int)s_hist[bb - 1];
        int en = (int)s_hist[bb];
        if (en > MAXE) en = MAXE;
        #pragma unroll 1
        for (int i = st + 1; i < en; i++) {
            unsigned long long k = s_keys[i];
            int j = i - 1;
            while (j >= st && s_keys[j] > k) {
                s_keys[j + 1] = s_keys[j];
                j--;
            }
            s_keys[j + 1] = k;
        }
    }
    __syncthreads();

    // ---- output: w + gathered pathway words, coalesced ----
    for (int i = tid; i < n; i += ST) {
        unsigned long long k = s_keys[i];
        int gene = (int)(k & 0x1FFFull);
        unsigned u = ~((unsigned)(k >> 13));
        unsigned absbits = (u & 0x80000000u) ? (u & 0x7FFFFFFFu)
                                             : ((~u) & 0x7FFFFFFFu);
        int pos = base + i;
        d_sw[b * NPOS + pos]  = sqrtf(sqrtf(__uint_as_float(absbits)));
        d_h01[b * NPOS + pos] = make_uint2(d_gbits[2 * gene], d_gbits[2 * gene + 1]);
    }
    // pads: forced hit (all pathways), w = 0
    if (r == NSPL - 1) {
        for (int pos = GN + tid; pos < NPOS; pos += ST) {
            d_sw[b * NPOS + pos]  = 0.0f;
            d_h01[b * NPOS + pos] = make_uint2(0xFFFFFFFFu, 0xFFFFFFFFu);
        }
    }
}

// ---------------------------------------------------------------------------
// K3: enrichment. Grid (BN, 10) x 160; warp w -> pathway part*5 + w.
// Builds its 5 pathways' position-mask words on the fly via ballot over the
// pre-gathered d_h01, then runs the two lane-local passes + warp scan.
// ---------------------------------------------------------------------------
__global__ void __launch_bounds__(160)
es_kernel(float* __restrict__ out) {
    __shared__ float    s_wt[32 * 161];    // 20608 B, stride-161 (conflict-free)
    __shared__ unsigned s_m5[5 * NWRD];    //  3200 B

    const int b    = blockIdx.x;
    const int part = blockIdx.y;
    const int tid  = threadIdx.x;
    const int wid  = tid >> 5;
    const int lane = tid & 31;
    const int pbase = part * 5;

    #pragma unroll
    for (int m = 0; m < 32; m++)
        s_wt[m * 161 + tid] = d_sw[b * NPOS + m * 160 + tid];

    // mask transpose: warp wid covers words [wid*32, wid*32+32)
    #pragma unroll 1
    for (int t = 0; t < 32; t++) {
        int wi = wid * 32 + t;
        uint2 h = d_h01[b * NPOS + wi * 32 + lane];
        #pragma unroll
        for (int j = 0; j < 5; j++) {
            int pp = pbase + j;
            unsigned hv = (pp >= 32) ? (h.y >> (pp - 32)) : (h.x >> pp);
            unsigned bm = __ballot_sync(0xffffffffu, hv & 1u);
            if (lane == j) s_m5[j * NWRD + wi] = bm;
        }
    }
    __syncthreads();

    // lane's 5 mask words -> registers
    unsigned m[5];
    #pragma unroll
    for (int j = 0; j < 5; j++) m[j] = s_m5[wid * NWRD + lane * 5 + j];

    const float* wrow = s_wt + lane * 161;

    // ---- pass A: hit count + hit-weight sum ----
    int c = __popc(m[0]) + __popc(m[1]) + __popc(m[2]) + __popc(m[3]) + __popc(m[4]);
    float hw = 0.0f;
    #pragma unroll
    for (int j = 0; j < 5; j++) {
        unsigned bits = m[j];
        #pragma unroll
        for (int q = 0; q < 32; q++) {
            float wv = wrow[j * 32 + q];
            if (bits & 1u) hw += wv;
            bits >>= 1;
        }
    }

    // warp totals
    float S = hw;
    int   th = c;
    #pragma unroll
    for (int off = 16; off; off >>= 1) {
        S  += __shfl_xor_sync(0xffffffffu, S, off);
        th += __shfl_xor_sync(0xffffffffu, th, off);
    }
    const int size = th - NPAD;

    const float invd = 1.0f / fmaxf((float)(GN - size), 1.0f);
    const float invS = (S > 0.0f) ? (1.0f / S) : 1.0f;

    // exclusive prefix of per-lane net delta
    float ld = hw * invS - (float)(SEGK - c) * invd;
    float v = ld;
    #pragma unroll
    for (int off = 1; off < 32; off <<= 1) {
        float n = __shfl_up_sync(0xffffffffu, v, off);
        if (lane >= off) v += n;
    }
    float r = v - ld;

    // ---- pass B: serial running sum, first argmax |r| ----
    float best_abs = -1.0f, best_val = 0.0f;
    int   best_idx = 0x7fffffff;
    #pragma unroll
    for (int j = 0; j < 5; j++) {
        unsigned bits = m[j];
        #pragma unroll
        for (int q = 0; q < 32; q++) {
            int k = j * 32 + q;
            float wv = wrow[k];
            r = (bits & 1u) ? fmaf(wv, invS, r) : (r - invd);
            bits >>= 1;
            float ar = fabsf(r);
            bool better = ar > best_abs;
            int i = lane * SEGK + k;
            best_abs = better ? ar : best_abs;
            best_val = better ? r  : best_val;
            best_idx = better ? i  : best_idx;
        }
    }

    // cross-lane argmax reduce (tie -> smallest index)
    #pragma unroll
    for (int off = 16; off; off >>= 1) {
        float oa = __shfl_down_sync(0xffffffffu, best_abs, off);
        float ov = __shfl_down_sync(0xffffffffu, best_val, off);
        int   oi = __shfl_down_sync(0xffffffffu, best_idx, off);
        if (oa > best_abs || (oa == best_abs && oi < best_idx)) {
            best_abs = oa; best_val = ov; best_idx = oi;
        }
    }
    if (lane == 0)
        out[b * PN + pbase + wid] = (size > 0) ? best_val : 0.0f;
}

// ---------------------------------------------------------------------------
extern "C" void kernel_launch(void* const* d_in, const int* in_sizes, int n_in,
                              void* d_out, int out_size) {
    const float* expr = (const float*)d_in[0];   // [B, G]
    const float* pw   = (const float*)d_in[1];   // [P, G]
    float* out        = (float*)d_out;           // [B, P]

    pbuild_kernel<<<20, 256>>>(pw);
    sort_kernel<<<dim3(BN, NSPL), ST>>>(expr);
    es_kernel<<<dim3(BN, 10), 160>>>(out);
}

// round 11
// speedup vs baseline: 1.1121x; 1.1121x over previous
#include <cuda_runtime.h>
#include <stdint.h>

#define BN 64
#define GN 4999
#define PN 50
#define PW 157             // pathway words (gene words)
#define NPOS 5120          // padded positions = 32*160
#define NWRD 160           // position words per pathway
#define SEGK 160           // positions per lane
#define NPAD 121           // NPOS - GN
#define NSPL 4             // range splits per sample
#define MAXE 2048          // max elements per range

__device__ __align__(16) unsigned d_pbits[PN * PW];  // pathway-major gene bits
__device__ __align__(16) float    d_sw[BN * NPOS];   // sorted |x|^.25 (natural)
__device__ __align__(16) int      d_sord[BN * NPOS]; // sorted gene ids

// bucket range splits at normal quartiles x = {+inf, .6745, 0, -.6745, -inf}
__constant__ int c_r[NSPL + 1] = {0, 3405, 4096, 4787, 8192};

// ---------------------------------------------------------------------------
// K1: pathway bitmask. One warp per (pathway, 32-gene word): 1 load + ballot.
// (R4 design, measured 4.3us.)
// ---------------------------------------------------------------------------
__global__ void pbuild_kernel(const float* __restrict__ pw) {
    const int p    = blockIdx.x;
    const int part = blockIdx.y;                  // 0..4
    const int wid  = threadIdx.x >> 5;            // 0..31
    const int lane = threadIdx.x & 31;
    const int word = part * 32 + wid;
    if (word >= PW) return;
    const int g = word * 32 + lane;
    bool hit = (g < GN) && (pw[(size_t)p * GN + g] > 0.0f);
    unsigned bits = __ballot_sync(0xffffffffu, hit);
    if (lane == 0) d_pbits[p * PW + word] = bits;
}

// ---------------------------------------------------------------------------
// K2: range-split bucket sort. Grid (BN, NSPL) x 512. Block (b, r) loads the
// full row, derives its global base = count(bucket < rlo) locally, sorts only
// buckets [rlo, rhi) via smem histogram/scan/scatter + per-bucket insertion
// sort on the full unique key, writes sorted w + gene ids (coalesced).
// ---------------------------------------------------------------------------
#define ST 512
#define EPT 10             // ceil(4999/512)

__global__ void __launch_bounds__(ST)
sort_kernel(const float* __restrict__ expr) {
    __shared__ unsigned s_hist[3584];            // owned-bin scan layout (7/thread)
    __shared__ unsigned long long s_keys[MAXE];
    __shared__ unsigned s_red[16];

    const int b    = blockIdx.x;
    const int r    = blockIdx.y;
    const int tid  = threadIdx.x;
    const int wid  = tid >> 5;
    const int lane = tid & 31;
    const int rlo  = c_r[r];
    const int rhi  = c_r[r + 1];
    const int nb   = rhi - rlo;
    const float* row = expr + (size_t)b * GN;

    for (int i = tid; i < 3584; i += ST) s_hist[i] = 0;
    __syncthreads();

    // ---- load full row, bucket, histogram own range, count below ----
    unsigned long long key[EPT];
    int bkt[EPT];
    int below = 0;
    #pragma unroll
    for (int j = 0; j < EPT; j++) {
        int i = j * ST + tid;
        if (i < GN) {
            float x = row[i];
            unsigned u = __float_as_uint(x);
            u = (u & 0x80000000u) ? ~u : (u | 0x80000000u);   // ascending map
            key[j] = ((unsigned long long)(~u) << 13) | (unsigned)i;
            int bb = (int)((4.0f - x) * 1024.0f);
            bb = bb < 0 ? 0 : (bb > 8191 ? 8191 : bb);
            bkt[j] = bb;
            below += (bb < rlo);
            if (bb >= rlo && bb < rhi) atomicAdd(&s_hist[bb - rlo], 1u);
        } else {
            bkt[j] = -1;
        }
    }

    // ---- block reduce 'below' -> base ----
    #pragma unroll
    for (int off = 16; off; off >>= 1) below += __shfl_down_sync(0xffffffffu, below, off);
    if (lane == 0) s_red[wid] = (unsigned)below;
    __syncthreads();
    int base = 0;
    #pragma unroll
    for (int q = 0; q < 16; q++) base += (int)s_red[q];
    __syncthreads();                              // s_red reused below

    // ---- exclusive scan over owned bins (7 per thread) ----
    {
        unsigned h[7], lsum = 0;
        #pragma unroll
        for (int q = 0; q < 7; q++) { h[q] = s_hist[tid * 7 + q]; lsum += h[q]; }
        unsigned v = lsum;
        #pragma unroll
        for (int off = 1; off < 32; off <<= 1) {
            unsigned n = __shfl_up_sync(0xffffffffu, v, off);
            if (lane >= off) v += n;
        }
        if (lane == 31) s_red[wid] = v;
        __syncthreads();
        if (wid == 0 && lane < 16) {
            unsigned wv = s_red[lane];
            unsigned vv = wv;
            #pragma unroll
            for (int off = 1; off < 16; off <<= 1) {
                unsigned n = __shfl_up_sync(0x0000ffffu, vv, off);
                if (lane >= off) vv += n;
            }
            s_red[lane] = vv - wv;                // exclusive warp bases
        }
        __syncthreads();
        unsigned run = s_red[wid] + (v - lsum);
        #pragma unroll
        for (int q = 0; q < 7; q++) { s_hist[tid * 7 + q] = run; run += h[q]; }
    }
    __syncthreads();

    // ---- scatter own elements ----
    #pragma unroll
    for (int j = 0; j < EPT; j++) {
        if (bkt[j] >= rlo && bkt[j] < rhi) {
            unsigned p = atomicAdd(&s_hist[bkt[j] - rlo], 1u);
            if (p < MAXE) s_keys[p] = key[j];
        }
    }
    __syncthreads();
    int n = (int)s_hist[nb - 1];                  // end of last own bucket
    if (n > MAXE) n = MAXE;

    // ---- insertion sort within buckets (full unique key) ----
    #pragma unroll 1
    for (int q = 0; q < 7; q++) {
        int bb = tid * 7 + q;
        if (bb >= nb) break;
        int st = (bb == 0) ? 0 : (int)s_hist[bb - 1];
        int en = (int)s_hist[bb];
        if (en > MAXE) en = MAXE;
        #pragma unroll 1
        for (int i = st + 1; i < en; i++) {
            unsigned long long k = s_keys[i];
            int j = i - 1;
            while (j >= st && s_keys[j] > k) {
                s_keys[j + 1] = s_keys[j];
                j--;
            }
            s_keys[j + 1] = k;
        }
    }
    __syncthreads();

    // ---- output: sorted w + gene ids, coalesced ----
    for (int i = tid; i < n; i += ST) {
        unsigned long long k = s_keys[i];
        int gene = (int)(k & 0x1FFFull);
        unsigned u = ~((unsigned)(k >> 13));
        unsigned absbits = (u & 0x80000000u) ? (u & 0x7FFFFFFFu)
                                             : ((~u) & 0x7FFFFFFFu);
        int pos = base + i;
        d_sw[b * NPOS + pos]   = sqrtf(sqrtf(__uint_as_float(absbits)));
        d_sord[b * NPOS + pos] = gene;
    }
    // pads: w = 0, gene = 0 (K3 forces pad positions to hit)
    if (r == NSPL - 1) {
        for (int pos = GN + tid; pos < NPOS; pos += ST) {
            d_sw[b * NPOS + pos]   = 0.0f;
            d_sord[b * NPOS + pos] = 0;
        }
    }
}

// ---------------------------------------------------------------------------
// K3: enrichment. Grid (BN, 10) x 160; warp w -> pathway part*5 + w.
// Loads sorted gene ids + its 5 pathways' gene bits into smem, transposes to
// position-indexed mask words via smem-only ballots (independent groups,
// unrolled), then runs the two lane-local passes + warp scan (R9 math).
// ---------------------------------------------------------------------------
__global__ void __launch_bounds__(160)
es_kernel(float* __restrict__ out) {
    __shared__ float    s_wt[32 * 161];    // 20608 B, stride-161 (conflict-free)
    __shared__ int      s_ord[NPOS];       // 20480 B
    __shared__ unsigned s_pb[5 * PW];      //  3140 B
    __shared__ unsigned s_m5[5 * NWRD];    //  3200 B

    const int b    = blockIdx.x;
    const int part = blockIdx.y;
    const int tid  = threadIdx.x;
    const int wid  = tid >> 5;
    const int lane = tid & 31;
    const int pbase = part * 5;

    #pragma unroll
    for (int m = 0; m < 32; m++) {
        s_wt[m * 161 + tid] = d_sw[b * NPOS + m * 160 + tid];
        s_ord[m * 160 + tid] = d_sord[b * NPOS + m * 160 + tid];
    }
    for (int i = tid; i < 5 * PW; i += 160)
        s_pb[i] = d_pbits[pbase * PW + i];
    __syncthreads();

    // ---- smem-only ballot transpose: warp wid does groups wid, wid+5, ... ----
    #pragma unroll
    for (int t = 0; t < 32; t++) {
        int wi = wid + t * 5;                     // 0..159
        int g  = s_ord[wi * 32 + lane];
        int wd = g >> 5, sh = g & 31;
        unsigned padm = (wi == 156) ? 0xFFFFFF80u : ((wi > 156) ? 0xFFFFFFFFu : 0u);
        #pragma unroll
        for (int j = 0; j < 5; j++) {
            unsigned bm = __ballot_sync(0xffffffffu, (s_pb[j * PW + wd] >> sh) & 1u);
            if (lane == j) s_m5[j * NWRD + wi] = bm | padm;
        }
    }
    __syncthreads();

    // lane's 5 mask words -> registers (stride-5: conflict-free)
    unsigned m[5];
    #pragma unroll
    for (int j = 0; j < 5; j++) m[j] = s_m5[wid * NWRD + lane * 5 + j];

    const float* wrow = s_wt + lane * 161;

    // ---- pass A: hit count + hit-weight sum ----
    int c = __popc(m[0]) + __popc(m[1]) + __popc(m[2]) + __popc(m[3]) + __popc(m[4]);
    float hw = 0.0f;
    #pragma unroll
    for (int j = 0; j < 5; j++) {
        unsigned bits = m[j];
        #pragma unroll
        for (int q = 0; q < 32; q++) {
            float wv = wrow[j * 32 + q];
            if (bits & 1u) hw += wv;
            bits >>= 1;
        }
    }

    // warp totals
    float S = hw;
    int   th = c;
    #pragma unroll
    for (int off = 16; off; off >>= 1) {
        S  += __shfl_xor_sync(0xffffffffu, S, off);
        th += __shfl_xor_sync(0xffffffffu, th, off);
    }
    const int size = th - NPAD;            // pads (forced hits, w=0)

    const float invd = 1.0f / fmaxf((float)(GN - size), 1.0f);
    const float invS = (S > 0.0f) ? (1.0f / S) : 1.0f;

    // exclusive prefix of per-lane net delta -> lane's starting r
    float ld = hw * invS - (float)(SEGK - c) * invd;
    float v = ld;
    #pragma unroll
    for (int off = 1; off < 32; off <<= 1) {
        float n = __shfl_up_sync(0xffffffffu, v, off);
        if (lane >= off) v += n;
    }
    float r = v - ld;                      // exclusive prefix

    // ---- pass B: serial running sum, track first argmax |r| ----
    float best_abs = -1.0f, best_val = 0.0f;
    int   best_idx = 0x7fffffff;
    #pragma unroll
    for (int j = 0; j < 5; j++) {
        unsigned bits = m[j];
        #pragma unroll
        for (int q = 0; q < 32; q++) {
            int k = j * 32 + q;
            float wv = wrow[k];
            r = (bits & 1u) ? fmaf(wv, invS, r) : (r - invd);
            bits >>= 1;
            float ar = fabsf(r);
            bool better = ar > best_abs;
            int i = lane * SEGK + k;
            best_abs = better ? ar : best_abs;
            best_val = better ? r  : best_val;
            best_idx = better ? i  : best_idx;
        }
    }

    // cross-lane argmax reduce (tie -> smallest index; pads can never win)
    #pragma unroll
    for (int off = 16; off; off >>= 1) {
        float oa = __shfl_down_sync(0xffffffffu, best_abs, off);
        float ov = __shfl_down_sync(0xffffffffu, best_val, off);
        int   oi = __shfl_down_sync(0xffffffffu, best_idx, off);
        if (oa > best_abs || (oa == best_abs && oi < best_idx)) {
            best_abs = oa; best_val = ov; best_idx = oi;
        }
    }
    if (lane == 0)
        out[b * PN + pbase + wid] = (size > 0) ? best_val : 0.0f;
}

// ---------------------------------------------------------------------------
extern "C" void kernel_launch(void* const* d_in, const int* in_sizes, int n_in,
                              void* d_out, int out_size) {
    const float* expr = (const float*)d_in[0];   // [B, G]
    const float* pw   = (const float*)d_in[1];   // [P, G]
    float* out        = (float*)d_out;           // [B, P]

    sort_kernel<<<dim3(BN, NSPL), ST>>>(expr);
    pbuild_kernel<<<dim3(PN, 5), 1024>>>(pw);
    es_kernel<<<dim3(BN, 10), 160>>>(out);
}